// round 13
// baseline (speedup 1.0000x reference)
#include <cuda_runtime.h>
#include <cuda_fp16.h>
#include <math.h>

#define N_NODES 50000
#define E_EDGES 1600000
#define B_BATCH 64
#define NB (N_NODES * B_BATCH)

// ---------------------------------------------------------------------------
// Scratch (__device__ globals; allocation-free). All fp16, 16B-aligned for
// uint4 loads and red.global.add.noftz.v4.f16x2 (misalign = err715 trap).
// Zero-invariant: g_msg_* are zero at kernel_launch entry (zero-initialized
// at module load; final_kernel re-zeros the chunks it reads every call).
// ---------------------------------------------------------------------------
__device__ __align__(16) __half g_xt[NB];      // x node-major fp16 [N][64]
__device__ __align__(16) __half g_msg_r[NB];   // reaction messages  (fp16 accum)
__device__ __align__(16) __half g_msg_d[NB];   // diffusion messages (fp16 accum)
__device__ float g_col_r[N_NODES];
__device__ float g_col_d[N_NODES];

__device__ __forceinline__ void red_v4_f16x2(__half* p, uint4 v) {
    unsigned long long gp;
    asm("cvta.to.global.u64 %0, %1;" : "=l"(gp) : "l"(p));
    asm volatile("red.global.add.noftz.v4.f16x2 [%0], {%1,%2,%3,%4};"
                 :: "l"(gp), "r"(v.x), "r"(v.y), "r"(v.z), "r"(v.w)
                 : "memory");
}

// scale 8 halves (uint4) by fp32 w, fp32 intermediate math, repack to f16x2
__device__ __forceinline__ uint4 scale8h(uint4 h, float w) {
    uint4 r;
    const unsigned* hp = &h.x;
    unsigned* rp = &r.x;
    #pragma unroll
    for (int k = 0; k < 4; k++) {
        float2 f = __half22float2(*reinterpret_cast<const __half2*>(&hp[k]));
        f.x *= w; f.y *= w;
        *reinterpret_cast<__half2*>(&rp[k]) = __float22half2_rn(f);
    }
    return r;
}

__device__ __forceinline__ float tanh_fast(float v) {
    float r;
    asm("tanh.approx.f32 %0, %1;" : "=f"(r) : "f"(v));
    return r;
}

// ---------------------------------------------------------------------------
// 1. Transpose x [B,N] -> g_xt [N][64] fp16 + zero col arrays (400KB only;
//    the 12.8MB msg zeroing lives in final_kernel's tail now).
//    Grid (1563, 2) x 256 thr, 4.2KB smem, float4 loads, uint2 fp16 stores.
// ---------------------------------------------------------------------------
__global__ void transpose_kernel(const float* __restrict__ x) {
    __shared__ float tile[32 * 33];
    int tid = threadIdx.x;          // 0..255

    // ---- col zero (cheap) ----
    {
        long flat = ((long)blockIdx.y * gridDim.x + blockIdx.x) * 256 + tid;
        if (flat < N_NODES) {
            g_col_r[flat] = 0.f;
            g_col_d[flat] = 0.f;
        }
    }

    // ---- transpose phase: 32 nodes x 32 batches per block ----
    int v0 = blockIdx.x * 32;
    int b0 = blockIdx.y * 32;

    // load: brow = tid/8 (0..31), txc = tid%8 (float4 chunk), 1 load/thread.
    {
        int brow = tid >> 3;
        int txc  = tid & 7;
        int vbase = v0 + txc * 4;   // N % 4 == 0: chunk all-valid or all-out
        if (vbase < N_NODES) {
            int b = b0 + brow;
            float4 xv = *reinterpret_cast<const float4*>(&x[(long)b * N_NODES + vbase]);
            tile[(txc * 4 + 0) * 33 + brow] = xv.x;
            tile[(txc * 4 + 1) * 33 + brow] = xv.y;
            tile[(txc * 4 + 2) * 33 + brow] = xv.z;
            tile[(txc * 4 + 3) * 33 + brow] = xv.w;
        }
    }
    __syncthreads();

    // store: vl = tid/8 (node), c = tid%8 (4-batch chunk) -> uint2 (4 halves)
    {
        int vl = tid >> 3;
        int c  = tid & 7;
        int v  = v0 + vl;
        if (v < N_NODES) {
            float2 fa = make_float2(tile[vl * 33 + c * 4 + 0], tile[vl * 33 + c * 4 + 1]);
            float2 fb = make_float2(tile[vl * 33 + c * 4 + 2], tile[vl * 33 + c * 4 + 3]);
            uint2 hw;
            *reinterpret_cast<__half2*>(&hw.x) = __float22half2_rn(fa);
            *reinterpret_cast<__half2*>(&hw.y) = __float22half2_rn(fb);
            *reinterpret_cast<uint2*>(&g_xt[(size_t)v * B_BATCH + b0 + c * 4]) = hw;
        }
    }
}

// ---------------------------------------------------------------------------
// 2. Edge scatter: 8 threads/edge, each handles 8 batches (16B fp16).
//    Per edge: 16 vector REDs (f16x2.v4) + 2 scalar col atomics.
//      msg_r[i][:] += w_r * x[j][:]    col_r[j] += w_r
//      msg_d[j][:] += w_d * x[i][:]    col_d[i] += w_d
//    (unchanged — at the LTS byte ceiling)
// ---------------------------------------------------------------------------
__global__ void edge_kernel(const int* __restrict__ ei,
                            const int* __restrict__ ej,
                            const float* __restrict__ wr,
                            const float* __restrict__ wd) {
    long tid = (long)blockIdx.x * blockDim.x + threadIdx.x;
    int e = (int)(tid >> 3);
    int t = (int)(tid & 7);
    if (e >= E_EDGES) return;

    int i = ei[e];
    int j = ej[e];
    float w1 = wr[e];
    float w2 = wd[e];

    const uint4* rowj = reinterpret_cast<const uint4*>(g_xt + (size_t)j * B_BATCH);
    const uint4* rowi = reinterpret_cast<const uint4*>(g_xt + (size_t)i * B_BATCH);
    uint4 hj = rowj[t];
    uint4 hi = rowi[t];

    red_v4_f16x2(g_msg_r + (size_t)i * B_BATCH + t * 8, scale8h(hj, w1));
    red_v4_f16x2(g_msg_d + (size_t)j * B_BATCH + t * 8, scale8h(hi, w2));

    if (t == 0) {
        atomicAdd(&g_col_r[j], w1);
        atomicAdd(&g_col_d[i], w2);
    }
}

// ---------------------------------------------------------------------------
// 3. Epilogue: 64-node tiles, 512 threads, 8 threads/node x 8 batches.
//    x comes from g_xt (fp16, L2-hot, node-major) — no fp32 x re-read, no
//    input smem tile. After reading its msg chunks, each thread re-zeros
//    them (private 16B slots -> race-free), restoring the zero-invariant
//    for the next graph replay.
// ---------------------------------------------------------------------------
__global__ void final_kernel(const float* __restrict__ bias_r,
                             const float* __restrict__ bias_d,
                             float* __restrict__ out) {
    __shared__ float so[64 * 65];   // out tile, node-major
    int V0 = blockIdx.x * 64;
    int tid = threadIdx.x;          // 0..511

    // compute: vl = node in tile (tid/8), q = 8-batch chunk (tid%8)
    {
        int vl = tid >> 3;
        int q  = tid & 7;
        int v  = V0 + vl;
        if (v < N_NODES) {
            size_t base = (size_t)v * B_BATCH + q * 8;
            uint4 xh4 = *reinterpret_cast<const uint4*>(&g_xt[base]);
            uint4 mr4 = *reinterpret_cast<const uint4*>(&g_msg_r[base]);
            uint4 md4 = *reinterpret_cast<const uint4*>(&g_msg_d[base]);
            float cr = g_col_r[v];
            float cd = g_col_d[v];
            float b1 = bias_r[v];
            float b2 = bias_d[v];
            const unsigned* xp  = &xh4.x;
            const unsigned* mrp = &mr4.x;
            const unsigned* mdp = &md4.x;
            #pragma unroll
            for (int c = 0; c < 4; c++) {
                float2 xv = __half22float2(*reinterpret_cast<const __half2*>(&xp[c]));
                float2 mr = __half22float2(*reinterpret_cast<const __half2*>(&mrp[c]));
                float2 md = __half22float2(*reinterpret_cast<const __half2*>(&mdp[c]));
                float r0 = fmaf(cr, xv.x, -mr.x) + b1;
                float r1 = fmaf(cr, xv.y, -mr.y) + b1;
                float d0 = fmaf(cd, xv.x, -md.x) + b2;
                float d1 = fmaf(cd, xv.y, -md.y) + b2;
                so[vl * 65 + q * 8 + 2 * c]     = tanh_fast(r0) + d0 + xv.x;
                so[vl * 65 + q * 8 + 2 * c + 1] = tanh_fast(r1) + d1 + xv.y;
            }
            // restore zero-invariant for next replay (private slots)
            uint4 z = make_uint4(0, 0, 0, 0);
            *reinterpret_cast<uint4*>(&g_msg_r[base]) = z;
            *reinterpret_cast<uint4*>(&g_msg_d[base]) = z;
        }
    }
    __syncthreads();

    // write out coalesced float4 along v: b = tid/8, vg = tid%8, 2 chunks
    {
        int b  = tid >> 3;
        int vg = tid & 7;
        #pragma unroll
        for (int r = 0; r < 2; r++) {
            int vbase = V0 + (vg + r * 8) * 4;
            if (vbase < N_NODES) {
                int vl = (vg + r * 8) * 4;
                float4 o;
                o.x = so[(vl + 0) * 65 + b];
                o.y = so[(vl + 1) * 65 + b];
                o.z = so[(vl + 2) * 65 + b];
                o.w = so[(vl + 3) * 65 + b];
                *reinterpret_cast<float4*>(&out[(long)b * N_NODES + vbase]) = o;
            }
        }
    }
}

// ---------------------------------------------------------------------------
extern "C" void kernel_launch(void* const* d_in, const int* in_sizes, int n_in,
                              void* d_out, int out_size) {
    // order: t, input, edge_i, edge_j, weight_react, weight_diff,
    //        bias_reaction, bias_diffusion
    const float* x  = (const float*)d_in[1];
    const int*   ei = (const int*)d_in[2];
    const int*   ej = (const int*)d_in[3];
    const float* wr = (const float*)d_in[4];
    const float* wd = (const float*)d_in[5];
    const float* br = (const float*)d_in[6];
    const float* bd = (const float*)d_in[7];
    float* out = (float*)d_out;

    dim3 tg((N_NODES + 31) / 32, B_BATCH / 32);   // (1563, 2) x 256 thr
    transpose_kernel<<<tg, 256>>>(x);

    long edge_threads = (long)E_EDGES * 8;
    edge_kernel<<<(unsigned)((edge_threads + 255) / 256), 256>>>(ei, ej, wr, wd);

    final_kernel<<<(N_NODES + 63) / 64, 512>>>(br, bd, out);
}

// round 14
// speedup vs baseline: 1.0600x; 1.0600x over previous
#include <cuda_runtime.h>
#include <cuda_fp16.h>
#include <math.h>

#define N_NODES 50000
#define E_EDGES 1600000
#define B_BATCH 64
#define NB (N_NODES * B_BATCH)

// ---------------------------------------------------------------------------
// Scratch (__device__ globals; allocation-free). All fp16, 16B-aligned for
// uint4 loads and red.global.add.noftz.v4.f16x2 (misalign = err715 trap).
// ---------------------------------------------------------------------------
__device__ __align__(16) __half g_xt[NB];      // x node-major fp16 [N][64]
__device__ __align__(16) __half g_msg_r[NB];   // reaction messages  (fp16 accum)
__device__ __align__(16) __half g_msg_d[NB];   // diffusion messages (fp16 accum)
__device__ float g_col_r[N_NODES];
__device__ float g_col_d[N_NODES];

__device__ __forceinline__ void red_v4_f16x2(__half* p, uint4 v) {
    unsigned long long gp;
    asm("cvta.to.global.u64 %0, %1;" : "=l"(gp) : "l"(p));
    asm volatile("red.global.add.noftz.v4.f16x2 [%0], {%1,%2,%3,%4};"
                 :: "l"(gp), "r"(v.x), "r"(v.y), "r"(v.z), "r"(v.w)
                 : "memory");
}

// scale 8 halves (uint4) by fp32 w, fp32 intermediate math, repack to f16x2
__device__ __forceinline__ uint4 scale8h(uint4 h, float w) {
    uint4 r;
    const unsigned* hp = &h.x;
    unsigned* rp = &r.x;
    #pragma unroll
    for (int k = 0; k < 4; k++) {
        float2 f = __half22float2(*reinterpret_cast<const __half2*>(&hp[k]));
        f.x *= w; f.y *= w;
        *reinterpret_cast<__half2*>(&rp[k]) = __float22half2_rn(f);
    }
    return r;
}

__device__ __forceinline__ float tanh_fast(float v) {
    float r;
    asm("tanh.approx.f32 %0, %1;" : "=f"(r) : "f"(v));
    return r;
}

// ---------------------------------------------------------------------------
// 1. Fused zero + transpose, ILP-2. Grid 1563 x 256 thr, 8.3KB smem.
//    Each block: 32 nodes x ALL 64 batches. Per thread: 2 float4 loads
//    (MLP=2), one uint4 fp16 store (8 batches). Msg zeroing stays here
//    (2 uint4/thread: 800256 >= 2*400000), priming L2 before the edge scatter.
// ---------------------------------------------------------------------------
__global__ void transpose_zero_kernel(const float* __restrict__ x) {
    __shared__ float tile[32 * 65];   // [node][batch], pad 65
    int tid = threadIdx.x;            // 0..255

    // ---- zero phase ----
    {
        const int Q = NB / 8;         // 400000 uint4 per msg buffer
        const long STRIDE = 1563L * 256L;   // 400128 threads
        long flat = (long)blockIdx.x * 256 + tid;
        uint4 z = make_uint4(0, 0, 0, 0);
        #pragma unroll
        for (int k = 0; k < 2; k++) {
            long idx = flat + k * STRIDE;
            if (idx < Q) {
                reinterpret_cast<uint4*>(g_msg_r)[idx] = z;
            } else if (idx < 2 * Q) {
                reinterpret_cast<uint4*>(g_msg_d)[idx - Q] = z;
            }
        }
        if (flat < N_NODES) {
            g_col_r[flat] = 0.f;
            g_col_d[flat] = 0.f;
        }
    }

    int v0 = blockIdx.x * 32;

    // load: brow = tid/8 (0..31), txc = tid%8 -> float4 of 4 nodes; two
    // independent loads (batch halves b and b+32). smem write addr
    // (4txc+k)*65 + b: mod 32 = 4txc+k+brow, lane-unique -> conflict-free.
    {
        int brow = tid >> 3;
        int txc  = tid & 7;
        int vbase = v0 + txc * 4;     // N % 4 == 0: chunk all-valid or all-out
        if (vbase < N_NODES) {
            #pragma unroll
            for (int h = 0; h < 2; h++) {
                int b = brow + h * 32;
                float4 xv = *reinterpret_cast<const float4*>(&x[(long)b * N_NODES + vbase]);
                tile[(txc * 4 + 0) * 65 + b] = xv.x;
                tile[(txc * 4 + 1) * 65 + b] = xv.y;
                tile[(txc * 4 + 2) * 65 + b] = xv.z;
                tile[(txc * 4 + 3) * 65 + b] = xv.w;
            }
        }
    }
    __syncthreads();

    // store: vl = tid/8 (node), q = tid%8 (8-batch chunk) -> one uint4
    {
        int vl = tid >> 3;
        int q  = tid & 7;
        int v  = v0 + vl;
        if (v < N_NODES) {
            unsigned hw[4];
            #pragma unroll
            for (int c = 0; c < 4; c++) {
                float2 f = make_float2(tile[vl * 65 + q * 8 + 2 * c],
                                       tile[vl * 65 + q * 8 + 2 * c + 1]);
                *reinterpret_cast<__half2*>(&hw[c]) = __float22half2_rn(f);
            }
            *reinterpret_cast<uint4*>(&g_xt[(size_t)v * B_BATCH + q * 8]) =
                make_uint4(hw[0], hw[1], hw[2], hw[3]);
        }
    }
}

// ---------------------------------------------------------------------------
// 2. Edge scatter: 8 threads/edge, each handles 8 batches (16B fp16).
//    Per edge: 16 vector REDs (f16x2.v4) + 2 scalar col atomics.
//      msg_r[i][:] += w_r * x[j][:]    col_r[j] += w_r
//      msg_d[j][:] += w_d * x[i][:]    col_d[i] += w_d
//    (unchanged — at the LTS byte ceiling)
// ---------------------------------------------------------------------------
__global__ void edge_kernel(const int* __restrict__ ei,
                            const int* __restrict__ ej,
                            const float* __restrict__ wr,
                            const float* __restrict__ wd) {
    long tid = (long)blockIdx.x * blockDim.x + threadIdx.x;
    int e = (int)(tid >> 3);
    int t = (int)(tid & 7);
    if (e >= E_EDGES) return;

    int i = ei[e];
    int j = ej[e];
    float w1 = wr[e];
    float w2 = wd[e];

    const uint4* rowj = reinterpret_cast<const uint4*>(g_xt + (size_t)j * B_BATCH);
    const uint4* rowi = reinterpret_cast<const uint4*>(g_xt + (size_t)i * B_BATCH);
    uint4 hj = rowj[t];
    uint4 hi = rowi[t];

    red_v4_f16x2(g_msg_r + (size_t)i * B_BATCH + t * 8, scale8h(hj, w1));
    red_v4_f16x2(g_msg_d + (size_t)j * B_BATCH + t * 8, scale8h(hi, w2));

    if (t == 0) {
        atomicAdd(&g_col_r[j], w1);
        atomicAdd(&g_col_d[i], w2);
    }
}

// ---------------------------------------------------------------------------
// 3. Epilogue: 64-node tiles, 512 threads, 8 threads/node x 8 batches.
//    x comes from g_xt (fp16, L2-hot) — no fp32 x re-read, no input smem
//    tile. NO tail zeroing (R13 lesson: keep zeroing before the scatter).
// ---------------------------------------------------------------------------
__global__ void final_kernel(const float* __restrict__ bias_r,
                             const float* __restrict__ bias_d,
                             float* __restrict__ out) {
    __shared__ float so[64 * 65];   // out tile, node-major
    int V0 = blockIdx.x * 64;
    int tid = threadIdx.x;          // 0..511

    // compute: vl = node in tile (tid/8), q = 8-batch chunk (tid%8)
    {
        int vl = tid >> 3;
        int q  = tid & 7;
        int v  = V0 + vl;
        if (v < N_NODES) {
            size_t base = (size_t)v * B_BATCH + q * 8;
            uint4 xh4 = *reinterpret_cast<const uint4*>(&g_xt[base]);
            uint4 mr4 = *reinterpret_cast<const uint4*>(&g_msg_r[base]);
            uint4 md4 = *reinterpret_cast<const uint4*>(&g_msg_d[base]);
            float cr = g_col_r[v];
            float cd = g_col_d[v];
            float b1 = bias_r[v];
            float b2 = bias_d[v];
            const unsigned* xp  = &xh4.x;
            const unsigned* mrp = &mr4.x;
            const unsigned* mdp = &md4.x;
            #pragma unroll
            for (int c = 0; c < 4; c++) {
                float2 xv = __half22float2(*reinterpret_cast<const __half2*>(&xp[c]));
                float2 mr = __half22float2(*reinterpret_cast<const __half2*>(&mrp[c]));
                float2 md = __half22float2(*reinterpret_cast<const __half2*>(&mdp[c]));
                float r0 = fmaf(cr, xv.x, -mr.x) + b1;
                float r1 = fmaf(cr, xv.y, -mr.y) + b1;
                float d0 = fmaf(cd, xv.x, -md.x) + b2;
                float d1 = fmaf(cd, xv.y, -md.y) + b2;
                so[vl * 65 + q * 8 + 2 * c]     = tanh_fast(r0) + d0 + xv.x;
                so[vl * 65 + q * 8 + 2 * c + 1] = tanh_fast(r1) + d1 + xv.y;
            }
        }
    }
    __syncthreads();

    // write out coalesced float4 along v: b = tid/8, vg = tid%8, 2 chunks
    {
        int b  = tid >> 3;
        int vg = tid & 7;
        #pragma unroll
        for (int r = 0; r < 2; r++) {
            int vbase = V0 + (vg + r * 8) * 4;
            if (vbase < N_NODES) {
                int vl = (vg + r * 8) * 4;
                float4 o;
                o.x = so[(vl + 0) * 65 + b];
                o.y = so[(vl + 1) * 65 + b];
                o.z = so[(vl + 2) * 65 + b];
                o.w = so[(vl + 3) * 65 + b];
                *reinterpret_cast<float4*>(&out[(long)b * N_NODES + vbase]) = o;
            }
        }
    }
}

// ---------------------------------------------------------------------------
extern "C" void kernel_launch(void* const* d_in, const int* in_sizes, int n_in,
                              void* d_out, int out_size) {
    // order: t, input, edge_i, edge_j, weight_react, weight_diff,
    //        bias_reaction, bias_diffusion
    const float* x  = (const float*)d_in[1];
    const int*   ei = (const int*)d_in[2];
    const int*   ej = (const int*)d_in[3];
    const float* wr = (const float*)d_in[4];
    const float* wd = (const float*)d_in[5];
    const float* br = (const float*)d_in[6];
    const float* bd = (const float*)d_in[7];
    float* out = (float*)d_out;

    transpose_zero_kernel<<<(N_NODES + 31) / 32, 256>>>(x);   // 1563 blocks

    long edge_threads = (long)E_EDGES * 8;
    edge_kernel<<<(unsigned)((edge_threads + 255) / 256), 256>>>(ei, ej, wr, wd);

    final_kernel<<<(N_NODES + 63) / 64, 512>>>(br, bd, out);
}